// round 12
// baseline (speedup 1.0000x reference)
#include <cuda_runtime.h>
#include <cuda_bf16.h>

#define BB 4
#define SS 512
#define EE 512
#define UU 256

// ---------------- scratch (__device__ globals) ----------------
__device__ float g_K[BB * SS * UU];            // key_pre + b1 (fp32, scores input)
__device__ float g_Q[BB * SS * UU];            // qry_pre
__device__ float g_S[BB * SS * SS];            // raw scores (fp32)
__device__ float g_part[4 * 2048 * 512];       // 16MB split-K partials

// bf16 hi/lo planes, u32 = (bf16 x_{2k+1} << 16) | bf16 x_{2k}
__device__ unsigned g_AH[2 * 2048 * 256];      // h1,h2 row-major [which][row][k-pair]
__device__ unsigned g_AL[2 * 2048 * 256];
__device__ unsigned g_WH[2 * 256 * 256];       // w transposed [which][u][e-pair]
__device__ unsigned g_WL[2 * 256 * 256];
__device__ unsigned g_TH[4 * 512 * 256];       // h1 transposed [b][e][j-pair]
__device__ unsigned g_TL[4 * 512 * 256];
__device__ unsigned g_SH[2048 * 256];          // softmax probs [row][j-pair]
__device__ unsigned g_SL[2048 * 256];

// ---------------- helpers ----------------
__device__ __forceinline__ float tanh_ap(float x) {
    float y; asm("tanh.approx.f32 %0,%1;" : "=f"(y) : "f"(x)); return y;
}
__device__ __forceinline__ float ex2_ap(float x) {
    float y; asm("ex2.approx.f32 %0,%1;" : "=f"(y) : "f"(x)); return y;
}
__device__ __forceinline__ void cp16(void* dst, const void* src) {
    unsigned d = (unsigned)__cvta_generic_to_shared(dst);
    asm volatile("cp.async.ca.shared.global [%0],[%1],16;" :: "r"(d), "l"(src) : "memory");
}
__device__ __forceinline__ void bsplit2(float x0, float x1, unsigned& hi, unsigned& lo) {
    asm("cvt.rn.bf16x2.f32 %0, %1, %2;" : "=r"(hi) : "f"(x1), "f"(x0));
    float b0 = __uint_as_float(hi << 16);
    float b1 = __uint_as_float(hi & 0xffff0000u);
    float l0 = x0 - b0;
    float l1 = x1 - b1;
    asm("cvt.rn.bf16x2.f32 %0, %1, %2;" : "=r"(lo) : "f"(l1), "f"(l0));
}
__device__ __forceinline__ void mma16816(float* c, const unsigned* a,
                                         unsigned b0, unsigned b1) {
    asm volatile(
        "mma.sync.aligned.m16n8k16.row.col.f32.bf16.bf16.f32 "
        "{%0,%1,%2,%3}, {%4,%5,%6,%7}, {%8,%9}, {%0,%1,%2,%3};"
        : "+f"(c[0]), "+f"(c[1]), "+f"(c[2]), "+f"(c[3])
        : "r"(a[0]), "r"(a[1]), "r"(a[2]), "r"(a[3]), "r"(b0), "r"(b1));
}
__device__ __forceinline__ void ldm_x4(unsigned* r, const unsigned* smem_ptr) {
    unsigned a = (unsigned)__cvta_generic_to_shared(smem_ptr);
    asm volatile("ldmatrix.sync.aligned.m8n8.x4.shared.b16 {%0,%1,%2,%3}, [%4];"
                 : "=r"(r[0]), "=r"(r[1]), "=r"(r[2]), "=r"(r[3]) : "r"(a));
}

// 16B-granule XOR swizzle: row stride 8 u32 (32B), conflict-free ldmatrix.
#define SWZ(row, c) ((c) ^ ((((row) >> 2) & 1) << 2))

// ---------------------------------------------------------------------------
// Conversion kernels (unchanged).
// ---------------------------------------------------------------------------
__global__ void __launch_bounds__(256)
conv_rows(const float* __restrict__ h1, const float* __restrict__ h2)
{
    const int i = blockIdx.x * 256 + threadIdx.x;
    float4 v = (i < 262144) ? ((const float4*)h1)[i]
                            : ((const float4*)h2)[i - 262144];
    unsigned h0, l0, h1u, l1u;
    bsplit2(v.x, v.y, h0, l0);
    bsplit2(v.z, v.w, h1u, l1u);
    ((uint2*)g_AH)[i] = make_uint2(h0, h1u);
    ((uint2*)g_AL)[i] = make_uint2(l0, l1u);
}

__global__ void __launch_bounds__(256)
conv_w(const float* __restrict__ w)
{
    __shared__ float tsm[32][33];
    const int tx = threadIdx.x & 31, ty = threadIdx.x >> 5;
    const int c0 = blockIdx.x * 32;
    const int r0 = blockIdx.y * 32;
#pragma unroll
    for (int j = 0; j < 4; j++)
        tsm[ty + 8 * j][tx] = w[(size_t)(r0 + ty + 8 * j) * UU + c0 + tx];
    __syncthreads();
    const int oc = threadIdx.x >> 3;
    const int p  = threadIdx.x & 7;
    const int which = r0 >> 9;
    const int rl = r0 & 511;
    unsigned* oH = g_WH + which * 65536;
    unsigned* oL = g_WL + which * 65536;
    const size_t base = (size_t)(c0 + oc) * 256 + (rl >> 1);
    unsigned h0, l0, h1u, l1u;
    bsplit2(tsm[2 * p][oc],      tsm[2 * p + 1][oc],  h0, l0);
    bsplit2(tsm[2 * p + 16][oc], tsm[2 * p + 17][oc], h1u, l1u);
    oH[base + p] = h0;      oL[base + p] = l0;
    oH[base + p + 8] = h1u; oL[base + p + 8] = l1u;
}

__global__ void __launch_bounds__(256)
conv_h1T(const float* __restrict__ h1)
{
    __shared__ float tsm[32][33];
    const int tx = threadIdx.x & 31, ty = threadIdx.x >> 5;
    const int r0 = blockIdx.x * 32;
    const int c0 = blockIdx.y * 32;
    const int b  = blockIdx.z;
    const float* src = h1 + (size_t)b * SS * EE;
#pragma unroll
    for (int j = 0; j < 4; j++)
        tsm[ty + 8 * j][tx] = src[(size_t)(r0 + ty + 8 * j) * EE + c0 + tx];
    __syncthreads();
    const int oc = threadIdx.x >> 3;
    const int p  = threadIdx.x & 7;
    unsigned* oH = g_TH + (size_t)b * 131072;
    unsigned* oL = g_TL + (size_t)b * 131072;
    const size_t base = (size_t)(c0 + oc) * 256 + (r0 >> 1);
    unsigned h0, l0, h1u, l1u;
    bsplit2(tsm[2 * p][oc],      tsm[2 * p + 1][oc],  h0, l0);
    bsplit2(tsm[2 * p + 16][oc], tsm[2 * p + 17][oc], h1u, l1u);
    oH[base + p] = h0;      oL[base + p] = l0;
    oH[base + p + 8] = h1u; oL[base + p + 8] = l1u;
}

// ---------------------------------------------------------------------------
// 64x64 tile x K=128 chunk GEMM via mma.sync bf16 3x-split.
// 4 warps (2Mx2N, warp = m32xn32). 4-STAGE cp.async pipeline (wait_group 2),
// XOR-swizzled smem (8 u32 rows, no padding): 32KB/CTA total.
// ---------------------------------------------------------------------------
__device__ __forceinline__ void mma_tile(
    const unsigned* __restrict__ AH, const unsigned* __restrict__ AL,
    const unsigned* __restrict__ BH, const unsigned* __restrict__ BL,
    float* __restrict__ P, int ldp, int row0, int col0, int ku0)
{
    __shared__ unsigned sA[4][2][64][8];   // [buf][plane][row][u32], swizzled
    __shared__ unsigned sB[4][2][64][8];

    const int tid = threadIdx.x;
    const int w = tid >> 5, lane = tid & 31;
    const int wm = w >> 1, wn = w & 1;
    const int g = lane >> 2, t = lane & 3;
    const int fr = tid >> 1;                       // fill row 0..63
    const int fh = SWZ(fr, (tid & 1) << 2);        // fill u32 col (swizzled)

    // ldmatrix source lane mappings (swizzled column)
    const int a_row = 32 * wm + (lane & 15);
    const int a_col = SWZ(a_row, (lane & 16) ? 4 : 0);
    const int b_row = 32 * wn + ((lane & 16) ? 8 : 0) + (lane & 7);
    const int b_col = SWZ(b_row, (lane & 8) ? 4 : 0);

    const unsigned* arH = AH + (size_t)(row0 + fr) * 256 + ku0 + ((tid & 1) << 2);
    const unsigned* arL = AL + (size_t)(row0 + fr) * 256 + ku0 + ((tid & 1) << 2);
    const unsigned* brH = BH + (size_t)(col0 + fr) * 256 + ku0 + ((tid & 1) << 2);
    const unsigned* brL = BL + (size_t)(col0 + fr) * 256 + ku0 + ((tid & 1) << 2);

    float acc[2][4][4];
#pragma unroll
    for (int mi = 0; mi < 2; mi++)
#pragma unroll
        for (int nt = 0; nt < 4; nt++)
#pragma unroll
            for (int j = 0; j < 4; j++) acc[mi][nt][j] = 0.f;

    // prologue: prefetch chunks 0,1,2 into buffers 0,1,2
#pragma unroll
    for (int p = 0; p < 3; p++) {
        cp16(&sA[p][0][fr][fh], arH + p * 8);
        cp16(&sA[p][1][fr][fh], arL + p * 8);
        cp16(&sB[p][0][fr][fh], brH + p * 8);
        cp16(&sB[p][1][fr][fh], brL + p * 8);
        asm volatile("cp.async.commit_group;");
    }

#pragma unroll 1
    for (int c = 0; c < 8; c++) {
        // wait until chunk c's group is complete
        if (c < 6)       { asm volatile("cp.async.wait_group 2;"); }
        else if (c == 6) { asm volatile("cp.async.wait_group 1;"); }
        else             { asm volatile("cp.async.wait_group 0;"); }
        __syncthreads();   // all warps done with buffer (c+3)&3's old chunk

        if (c < 5) {       // prefetch chunk c+3 into buffer (c+3)&3
            const int nb = (c + 3) & 3;
            const int off = (c + 3) * 8;
            cp16(&sA[nb][0][fr][fh], arH + off);
            cp16(&sA[nb][1][fr][fh], arL + off);
            cp16(&sB[nb][0][fr][fh], brH + off);
            cp16(&sB[nb][1][fr][fh], brL + off);
            asm volatile("cp.async.commit_group;");
        }

        const int buf = c & 3;
        unsigned aH[2][4], aL[2][4], bH[2][4], bL[2][4];
        ldm_x4(aH[0], &sA[buf][0][a_row][a_col]);
        ldm_x4(aH[1], &sA[buf][0][16 + a_row][a_col]);
        ldm_x4(aL[0], &sA[buf][1][a_row][a_col]);
        ldm_x4(aL[1], &sA[buf][1][16 + a_row][a_col]);
        ldm_x4(bH[0], &sB[buf][0][b_row][b_col]);
        ldm_x4(bH[1], &sB[buf][0][16 + b_row][b_col]);
        ldm_x4(bL[0], &sB[buf][1][b_row][b_col]);
        ldm_x4(bL[1], &sB[buf][1][16 + b_row][b_col]);

#pragma unroll
        for (int mi = 0; mi < 2; mi++)
#pragma unroll
            for (int h = 0; h < 2; h++)
#pragma unroll
                for (int s = 0; s < 2; s++) {
                    const int nt = 2 * h + s;
                    mma16816(acc[mi][nt], aH[mi], bH[h][2 * s], bH[h][2 * s + 1]);
                    mma16816(acc[mi][nt], aH[mi], bL[h][2 * s], bL[h][2 * s + 1]);
                    mma16816(acc[mi][nt], aL[mi], bH[h][2 * s], bH[h][2 * s + 1]);
                }
    }

#pragma unroll
    for (int mi = 0; mi < 2; mi++) {
        const int orow = row0 + 32 * wm + 16 * mi + g;
#pragma unroll
        for (int nt = 0; nt < 4; nt++) {
            const int ocol = col0 + 32 * wn + 8 * nt + 2 * t;
            *(float2*)&P[(size_t)orow * ldp + ocol] =
                make_float2(acc[mi][nt][0], acc[mi][nt][1]);
            *(float2*)&P[(size_t)(orow + 8) * ldp + ocol] =
                make_float2(acc[mi][nt][2], acc[mi][nt][3]);
        }
    }
}

// Stage 1a: split-K partials, K = h1@w1 (which=0), Q = h2@w2 (which=1).
__global__ void __launch_bounds__(128)
qk_mma_split()
{
    const int which = blockIdx.z >> 2;
    const int ks    = blockIdx.z & 3;
    float* P = g_part + (size_t)(ks * 2 + which) * 2048 * 256;
    mma_tile(g_AH + (size_t)which * 524288, g_AL + (size_t)which * 524288,
             g_WH + which * 65536, g_WL + which * 65536,
             P, 256, blockIdx.y * 64, blockIdx.x * 64, ks * 64);
}

// Stage 1b: reduce partials -> g_K (+b1), g_Q. grid 1024, block 256.
__global__ void __launch_bounds__(256)
qk_reduce(const float* __restrict__ b1)
{
    const int tt = blockIdx.x * 256 + threadIdx.x;
    const int which = tt >> 17;
    const int i4 = tt & 131071;
    const float4* p = (const float4*)g_part + (size_t)which * 131072 + i4;
    float4 s0 = p[0];
    float4 s1 = p[262144];
    float4 s2 = p[524288];
    float4 s3 = p[786432];
    float4 o = make_float4((s0.x + s1.x) + (s2.x + s3.x),
                           (s0.y + s1.y) + (s2.y + s3.y),
                           (s0.z + s1.z) + (s2.z + s3.z),
                           (s0.w + s1.w) + (s2.w + s3.w));
    if (which == 0) {
        const float4 bv = ((const float4*)b1)[i4 & 63];
        o.x += bv.x; o.y += bv.y; o.z += bv.z; o.w += bv.w;
        ((float4*)g_K)[i4] = o;
    } else {
        ((float4*)g_Q)[i4] = o;
    }
}

// Stage 3a: split-K partials for out[b] = P[b] @ h1[b].
__global__ void __launch_bounds__(128)
pv_mma_split()
{
    const int b  = blockIdx.z >> 2;
    const int ks = blockIdx.z & 3;
    float* P = g_part + (size_t)ks * 2048 * 512 + (size_t)b * 512 * 512;
    mma_tile(g_SH + (size_t)b * 131072, g_SL + (size_t)b * 131072,
             g_TH + (size_t)b * 131072, g_TL + (size_t)b * 131072,
             P, 512, blockIdx.y * 64, blockIdx.x * 64, ks * 64);
}

// Stage 3b: reduce partials -> out. grid 1024, block 256.
__global__ void __launch_bounds__(256)
pv_reduce(float* __restrict__ out)
{
    const int i4 = blockIdx.x * 256 + threadIdx.x;
    const float4* p = (const float4*)g_part + i4;
    float4 s0 = p[0];
    float4 s1 = p[262144];
    float4 s2 = p[524288];
    float4 s3 = p[786432];
    ((float4*)out)[i4] = make_float4((s0.x + s1.x) + (s2.x + s3.x),
                                     (s0.y + s1.y) + (s2.y + s3.y),
                                     (s0.z + s1.z) + (s2.z + s3.z),
                                     (s0.w + s1.w) + (s2.w + s3.w));
}

// ---------------------------------------------------------------------------
// Stage 2a: scores (fp32, MUFU-floor bound, unchanged). b2 dropped.
// ---------------------------------------------------------------------------
__global__ void __launch_bounds__(256)
scores_kernel(const float* __restrict__ v)
{
    __shared__ float4 q4[32][32];
    __shared__ float4 k4[32][33];
    __shared__ float4 v4s[32];

    const int b  = blockIdx.z;
    const int it = blockIdx.y;
    const int jt = blockIdx.x;
    const int tid = threadIdx.x;
    const int jl = tid & 31;
    const int ib = tid >> 5;

    const float* Qb = g_Q + ((size_t)(b * SS + it * 32)) * UU;
    const float* Kb = g_K + ((size_t)(b * SS + jt * 32)) * UU;

    float acc[4] = {0.f, 0.f, 0.f, 0.f};

    for (int uc = 0; uc < 2; uc++) {
        const int base = uc * 32;
        for (int tix = tid; tix < 32 * 32; tix += 256) {
            const int r = tix >> 5, c = tix & 31;
            q4[r][c] = ((const float4*)(Qb + (size_t)r * UU))[base + c];
            k4[r][c] = ((const float4*)(Kb + (size_t)r * UU))[base + c];
        }
        if (tid < 32) v4s[tid] = ((const float4*)v)[base + tid];
        __syncthreads();

#pragma unroll 4
        for (int c = 0; c < 32; c++) {
            const float4 kv = k4[jl][c];
            const float4 vv = v4s[c];
#pragma unroll
            for (int r = 0; r < 4; r++) {
                const float4 qv = q4[ib + 8 * r][c];
                acc[r] += vv.x * tanh_ap(qv.x + kv.x);
                acc[r] += vv.y * tanh_ap(qv.y + kv.y);
                acc[r] += vv.z * tanh_ap(qv.z + kv.z);
                acc[r] += vv.w * tanh_ap(qv.w + kv.w);
            }
        }
        __syncthreads();
    }

#pragma unroll
    for (int r = 0; r < 4; r++) {
        const int i = it * 32 + ib + 8 * r;
        g_S[((size_t)(b * SS + i)) * SS + jt * 32 + jl] = acc[r];
    }
}

// Stage 2b: row softmax; emits bf16 hi/lo pair-planes for the pv mma.
__global__ void __launch_bounds__(256)
softmax2()
{
    const int row = blockIdx.x;
    const float* s = g_S + (size_t)row * SS;
    const int tid = threadIdx.x;

    const float2 vv = ((const float2*)s)[tid];
    float m = fmaxf(vv.x, vv.y);
#pragma unroll
    for (int o = 16; o > 0; o >>= 1) m = fmaxf(m, __shfl_xor_sync(0xffffffffu, m, o));
    __shared__ float sm[8];
    __shared__ float ssum[8];
    if ((tid & 31) == 0) sm[tid >> 5] = m;
    __syncthreads();
    float bm = sm[0];
#pragma unroll
    for (int i = 1; i < 8; i++) bm = fmaxf(bm, sm[i]);

    const float L2E = 1.4426950408889634f;
    float e0 = ex2_ap((vv.x - bm) * L2E);
    float e1 = ex2_ap((vv.y - bm) * L2E);
    float su = e0 + e1;
#pragma unroll
    for (int o = 16; o > 0; o >>= 1) su += __shfl_xor_sync(0xffffffffu, su, o);
    if ((tid & 31) == 0) ssum[tid >> 5] = su;
    __syncthreads();
    float bs = 0.f;
#pragma unroll
    for (int i = 0; i < 8; i++) bs += ssum[i];

    const float inv = 1.0f / bs;
    unsigned h, l;
    bsplit2(e0 * inv, e1 * inv, h, l);
    g_SH[(size_t)row * 256 + tid] = h;
    g_SL[(size_t)row * 256 + tid] = l;
}

extern "C" void kernel_launch(void* const* d_in, const int* in_sizes, int n_in,
                              void* d_out, int out_size)
{
    const float* h1 = (const float*)d_in[0];
    const float* h2 = (const float*)d_in[1];
    const float* w  = (const float*)d_in[2];
    const float* b1 = (const float*)d_in[3];
    const float* v  = (const float*)d_in[4];
    // b2 (d_in[5]) unused: softmax is shift-invariant.
    float* out = (float*)d_out;

    conv_rows<<<2048, 256>>>(h1, h2);
    conv_w<<<dim3(8, 32), 256>>>(w);
    conv_h1T<<<dim3(16, 16, 4), 256>>>(h1);

    qk_mma_split<<<dim3(4, 32, 8), 128>>>();
    qk_reduce<<<1024, 256>>>(b1);

    scores_kernel<<<dim3(16, 16, 4), 256>>>(v);
    softmax2<<<2048, 256>>>();

    pv_mma_split<<<dim3(8, 8, 16), 128>>>();
    pv_reduce<<<1024, 256>>>(out);
}

// round 14
// speedup vs baseline: 1.1186x; 1.1186x over previous
#include <cuda_runtime.h>
#include <cuda_bf16.h>

#define BB 4
#define SS 512
#define EE 512
#define UU 256

// ---------------- scratch (__device__ globals) ----------------
__device__ float g_K[BB * SS * UU];            // key_pre + b1 (fp32, scores input)
__device__ float g_Q[BB * SS * UU];            // qry_pre
__device__ float g_S[BB * SS * SS];            // raw scores (fp32)
__device__ float g_part[4 * 2048 * 512];       // 16MB split-K partials

// bf16 hi/lo planes, u32 = (bf16 x_{2k+1} << 16) | bf16 x_{2k}
__device__ unsigned g_AH[2 * 2048 * 256];      // h1,h2 row-major [which][row][k-pair]
__device__ unsigned g_AL[2 * 2048 * 256];
__device__ unsigned g_WH[2 * 256 * 256];       // w transposed [which][u][e-pair]
__device__ unsigned g_WL[2 * 256 * 256];
__device__ unsigned g_TH[4 * 512 * 256];       // h1 transposed [b][e][j-pair]
__device__ unsigned g_TL[4 * 512 * 256];
__device__ unsigned g_SH[2048 * 256];          // softmax probs [row][j-pair]
__device__ unsigned g_SL[2048 * 256];

// ---------------- helpers ----------------
__device__ __forceinline__ float tanh_ap(float x) {
    float y; asm("tanh.approx.f32 %0,%1;" : "=f"(y) : "f"(x)); return y;
}
__device__ __forceinline__ float ex2_ap(float x) {
    float y; asm("ex2.approx.f32 %0,%1;" : "=f"(y) : "f"(x)); return y;
}
__device__ __forceinline__ void cp16(void* dst, const void* src) {
    unsigned d = (unsigned)__cvta_generic_to_shared(dst);
    asm volatile("cp.async.ca.shared.global [%0],[%1],16;" :: "r"(d), "l"(src) : "memory");
}
__device__ __forceinline__ void bsplit2(float x0, float x1, unsigned& hi, unsigned& lo) {
    asm("cvt.rn.bf16x2.f32 %0, %1, %2;" : "=r"(hi) : "f"(x1), "f"(x0));
    float b0 = __uint_as_float(hi << 16);
    float b1 = __uint_as_float(hi & 0xffff0000u);
    float l0 = x0 - b0;
    float l1 = x1 - b1;
    asm("cvt.rn.bf16x2.f32 %0, %1, %2;" : "=r"(lo) : "f"(l1), "f"(l0));
}
__device__ __forceinline__ void mma16816(float* c, const unsigned* a,
                                         unsigned b0, unsigned b1) {
    asm volatile(
        "mma.sync.aligned.m16n8k16.row.col.f32.bf16.bf16.f32 "
        "{%0,%1,%2,%3}, {%4,%5,%6,%7}, {%8,%9}, {%0,%1,%2,%3};"
        : "+f"(c[0]), "+f"(c[1]), "+f"(c[2]), "+f"(c[3])
        : "r"(a[0]), "r"(a[1]), "r"(a[2]), "r"(a[3]), "r"(b0), "r"(b1));
}
__device__ __forceinline__ void ldm_x4(unsigned* r, const unsigned* smem_ptr) {
    unsigned a = (unsigned)__cvta_generic_to_shared(smem_ptr);
    asm volatile("ldmatrix.sync.aligned.m8n8.x4.shared.b16 {%0,%1,%2,%3}, [%4];"
                 : "=r"(r[0]), "=r"(r[1]), "=r"(r[2]), "=r"(r[3]) : "r"(a));
}

// ---------------------------------------------------------------------------
// Merged conversion kernel: grid 3328 CTAs x 256 threads.
//   [0, 2048)      conv_rows: h1,h2 -> g_AH/g_AL
//   [2048, 2304)   conv_w:    w -> g_WH/g_WL (transposed)
//   [2304, 3328)   conv_h1T:  h1 -> g_TH/g_TL (transposed)
// ---------------------------------------------------------------------------
__global__ void __launch_bounds__(256)
conv_all(const float* __restrict__ h1, const float* __restrict__ h2,
         const float* __restrict__ w)
{
    __shared__ float tsm[32][33];
    const int bid = blockIdx.x;

    if (bid < 2048) {
        const int i = bid * 256 + threadIdx.x;
        float4 v = (i < 262144) ? ((const float4*)h1)[i]
                                : ((const float4*)h2)[i - 262144];
        unsigned h0, l0, h1u, l1u;
        bsplit2(v.x, v.y, h0, l0);
        bsplit2(v.z, v.w, h1u, l1u);
        ((uint2*)g_AH)[i] = make_uint2(h0, h1u);
        ((uint2*)g_AL)[i] = make_uint2(l0, l1u);
        return;
    }

    const int tx = threadIdx.x & 31, ty = threadIdx.x >> 5;
    const int oc = threadIdx.x >> 3;
    const int p  = threadIdx.x & 7;

    if (bid < 2304) {
        const int idx = bid - 2048;
        const int c0 = (idx & 7) * 32;        // u
        const int r0 = (idx >> 3) * 32;       // e' in [0,1024)
#pragma unroll
        for (int j = 0; j < 4; j++)
            tsm[ty + 8 * j][tx] = w[(size_t)(r0 + ty + 8 * j) * UU + c0 + tx];
        __syncthreads();
        const int which = r0 >> 9;
        const int rl = r0 & 511;
        unsigned* oH = g_WH + which * 65536;
        unsigned* oL = g_WL + which * 65536;
        const size_t base = (size_t)(c0 + oc) * 256 + (rl >> 1);
        unsigned h0, l0, h1u, l1u;
        bsplit2(tsm[2 * p][oc],      tsm[2 * p + 1][oc],  h0, l0);
        bsplit2(tsm[2 * p + 16][oc], tsm[2 * p + 17][oc], h1u, l1u);
        oH[base + p] = h0;      oL[base + p] = l0;
        oH[base + p + 8] = h1u; oL[base + p + 8] = l1u;
        return;
    }

    {
        const int idx = bid - 2304;
        const int r0 = (idx & 15) * 32;           // j
        const int c0 = ((idx >> 4) & 15) * 32;    // e
        const int b  = idx >> 8;
        const float* src = h1 + (size_t)b * SS * EE;
#pragma unroll
        for (int j = 0; j < 4; j++)
            tsm[ty + 8 * j][tx] = src[(size_t)(r0 + ty + 8 * j) * EE + c0 + tx];
        __syncthreads();
        unsigned* oH = g_TH + (size_t)b * 131072;
        unsigned* oL = g_TL + (size_t)b * 131072;
        const size_t base = (size_t)(c0 + oc) * 256 + (r0 >> 1);
        unsigned h0, l0, h1u, l1u;
        bsplit2(tsm[2 * p][oc],      tsm[2 * p + 1][oc],  h0, l0);
        bsplit2(tsm[2 * p + 16][oc], tsm[2 * p + 17][oc], h1u, l1u);
        oH[base + p] = h0;      oL[base + p] = l0;
        oH[base + p + 8] = h1u; oL[base + p + 8] = l1u;
    }
}

// ---------------------------------------------------------------------------
// 64x64 tile x K=128 chunk GEMM via mma.sync bf16 3x-split.
// R11 base (measured best) with k32 chunks: 4 barriers instead of 8,
// 24 MMAs per warp per phase. Prefetch distance 1 (measured best).
// smem rows of 20 u32 (16 used): ldmatrix granules (5r+c) mod 8 = permutation.
// ---------------------------------------------------------------------------
__device__ __forceinline__ void mma_tile(
    const unsigned* __restrict__ AH, const unsigned* __restrict__ AL,
    const unsigned* __restrict__ BH, const unsigned* __restrict__ BL,
    float* __restrict__ P, int ldp, int row0, int col0, int ku0)
{
    __shared__ unsigned sA[2][2][64][20];   // [buf][plane][row][u32], 16 used
    __shared__ unsigned sB[2][2][64][20];

    const int tid = threadIdx.x;
    const int w = tid >> 5, lane = tid & 31;
    const int wm = w >> 1, wn = w & 1;
    const int g = lane >> 2, t = lane & 3;
    const int fr = tid >> 2;              // fill row 0..31 (and +32)
    const int fc = (tid & 3) << 2;        // fill u32 col 0/4/8/12

    const int a_row = 32 * wm + (lane & 15);
    const int a_colb = (lane & 16) ? 4 : 0;
    const int b_row = 32 * wn + ((lane & 16) ? 8 : 0) + (lane & 7);
    const int b_colb = (lane & 8) ? 4 : 0;

    const unsigned* arH = AH + (size_t)(row0 + fr) * 256 + ku0 + fc;
    const unsigned* arL = AL + (size_t)(row0 + fr) * 256 + ku0 + fc;
    const unsigned* brH = BH + (size_t)(col0 + fr) * 256 + ku0 + fc;
    const unsigned* brL = BL + (size_t)(col0 + fr) * 256 + ku0 + fc;

    float acc[2][4][4];
#pragma unroll
    for (int mi = 0; mi < 2; mi++)
#pragma unroll
        for (int nt = 0; nt < 4; nt++)
#pragma unroll
            for (int j = 0; j < 4; j++) acc[mi][nt][j] = 0.f;

    // fill chunk 0 (k32 = 16 u32 per row; rows fr and fr+32)
#pragma unroll
    for (int rh = 0; rh < 2; rh++) {
        const int off = rh * 32 * 256;
        cp16(&sA[0][0][fr + 32 * rh][fc], arH + off);
        cp16(&sA[0][1][fr + 32 * rh][fc], arL + off);
        cp16(&sB[0][0][fr + 32 * rh][fc], brH + off);
        cp16(&sB[0][1][fr + 32 * rh][fc], brL + off);
    }
    asm volatile("cp.async.commit_group;");

#pragma unroll 1
    for (int c = 0; c < 4; c++) {
        const int buf = c & 1;
        asm volatile("cp.async.wait_group 0;");
        __syncthreads();
        if (c < 3) {
            const int nb = buf ^ 1;
            const int koff = (c + 1) * 16;
#pragma unroll
            for (int rh = 0; rh < 2; rh++) {
                const int off = rh * 32 * 256 + koff;
                cp16(&sA[nb][0][fr + 32 * rh][fc], arH + off);
                cp16(&sA[nb][1][fr + 32 * rh][fc], arL + off);
                cp16(&sB[nb][0][fr + 32 * rh][fc], brH + off);
                cp16(&sB[nb][1][fr + 32 * rh][fc], brL + off);
            }
            asm volatile("cp.async.commit_group;");
        }

#pragma unroll
        for (int h = 0; h < 2; h++) {       // two k16 halves within the k32 chunk
            const int a_col = 8 * h + a_colb;
            const int b_col = 8 * h + b_colb;
            unsigned aH[2][4], aL[2][4], bH[2][4], bL[2][4];
            ldm_x4(aH[0], &sA[buf][0][a_row][a_col]);
            ldm_x4(aH[1], &sA[buf][0][16 + a_row][a_col]);
            ldm_x4(aL[0], &sA[buf][1][a_row][a_col]);
            ldm_x4(aL[1], &sA[buf][1][16 + a_row][a_col]);
            ldm_x4(bH[0], &sB[buf][0][b_row][b_col]);
            ldm_x4(bH[1], &sB[buf][0][16 + b_row][b_col]);
            ldm_x4(bL[0], &sB[buf][1][b_row][b_col]);
            ldm_x4(bL[1], &sB[buf][1][16 + b_row][b_col]);

#pragma unroll
            for (int mi = 0; mi < 2; mi++)
#pragma unroll
                for (int hh = 0; hh < 2; hh++)
#pragma unroll
                    for (int s = 0; s < 2; s++) {
                        const int nt = 2 * hh + s;
                        mma16816(acc[mi][nt], aH[mi], bH[hh][2 * s], bH[hh][2 * s + 1]);
                        mma16816(acc[mi][nt], aH[mi], bL[hh][2 * s], bL[hh][2 * s + 1]);
                        mma16816(acc[mi][nt], aL[mi], bH[hh][2 * s], bH[hh][2 * s + 1]);
                    }
        }
    }

#pragma unroll
    for (int mi = 0; mi < 2; mi++) {
        const int orow = row0 + 32 * wm + 16 * mi + g;
#pragma unroll
        for (int nt = 0; nt < 4; nt++) {
            const int ocol = col0 + 32 * wn + 8 * nt + 2 * t;
            *(float2*)&P[(size_t)orow * ldp + ocol] =
                make_float2(acc[mi][nt][0], acc[mi][nt][1]);
            *(float2*)&P[(size_t)(orow + 8) * ldp + ocol] =
                make_float2(acc[mi][nt][2], acc[mi][nt][3]);
        }
    }
}

// Stage 1a: split-K partials, K = h1@w1 (which=0), Q = h2@w2 (which=1).
__global__ void __launch_bounds__(128)
qk_mma_split()
{
    const int which = blockIdx.z >> 2;
    const int ks    = blockIdx.z & 3;
    float* P = g_part + (size_t)(ks * 2 + which) * 2048 * 256;
    mma_tile(g_AH + (size_t)which * 524288, g_AL + (size_t)which * 524288,
             g_WH + which * 65536, g_WL + which * 65536,
             P, 256, blockIdx.y * 64, blockIdx.x * 64, ks * 64);
}

// Stage 1b: reduce partials -> g_K (+b1), g_Q. grid 1024, block 256.
__global__ void __launch_bounds__(256)
qk_reduce(const float* __restrict__ b1)
{
    const int tt = blockIdx.x * 256 + threadIdx.x;
    const int which = tt >> 17;
    const int i4 = tt & 131071;
    const float4* p = (const float4*)g_part + (size_t)which * 131072 + i4;
    float4 s0 = p[0];
    float4 s1 = p[262144];
    float4 s2 = p[524288];
    float4 s3 = p[786432];
    float4 o = make_float4((s0.x + s1.x) + (s2.x + s3.x),
                           (s0.y + s1.y) + (s2.y + s3.y),
                           (s0.z + s1.z) + (s2.z + s3.z),
                           (s0.w + s1.w) + (s2.w + s3.w));
    if (which == 0) {
        const float4 bv = ((const float4*)b1)[i4 & 63];
        o.x += bv.x; o.y += bv.y; o.z += bv.z; o.w += bv.w;
        ((float4*)g_K)[i4] = o;
    } else {
        ((float4*)g_Q)[i4] = o;
    }
}

// Stage 3a: split-K partials for out[b] = P[b] @ h1[b].
__global__ void __launch_bounds__(128)
pv_mma_split()
{
    const int b  = blockIdx.z >> 2;
    const int ks = blockIdx.z & 3;
    float* P = g_part + (size_t)ks * 2048 * 512 + (size_t)b * 512 * 512;
    mma_tile(g_SH + (size_t)b * 131072, g_SL + (size_t)b * 131072,
             g_TH + (size_t)b * 131072, g_TL + (size_t)b * 131072,
             P, 512, blockIdx.y * 64, blockIdx.x * 64, ks * 64);
}

// Stage 3b: reduce partials -> out. grid 1024, block 256.
__global__ void __launch_bounds__(256)
pv_reduce(float* __restrict__ out)
{
    const int i4 = blockIdx.x * 256 + threadIdx.x;
    const float4* p = (const float4*)g_part + i4;
    float4 s0 = p[0];
    float4 s1 = p[262144];
    float4 s2 = p[524288];
    float4 s3 = p[786432];
    ((float4*)out)[i4] = make_float4((s0.x + s1.x) + (s2.x + s3.x),
                                     (s0.y + s1.y) + (s2.y + s3.y),
                                     (s0.z + s1.z) + (s2.z + s3.z),
                                     (s0.w + s1.w) + (s2.w + s3.w));
}

// ---------------------------------------------------------------------------
// Stage 2a: scores (fp32, MUFU-floor bound, unchanged). b2 dropped.
// ---------------------------------------------------------------------------
__global__ void __launch_bounds__(256)
scores_kernel(const float* __restrict__ v)
{
    __shared__ float4 q4[32][32];
    __shared__ float4 k4[32][33];
    __shared__ float4 v4s[32];

    const int b  = blockIdx.z;
    const int it = blockIdx.y;
    const int jt = blockIdx.x;
    const int tid = threadIdx.x;
    const int jl = tid & 31;
    const int ib = tid >> 5;

    const float* Qb = g_Q + ((size_t)(b * SS + it * 32)) * UU;
    const float* Kb = g_K + ((size_t)(b * SS + jt * 32)) * UU;

    float acc[4] = {0.f, 0.f, 0.f, 0.f};

    for (int uc = 0; uc < 2; uc++) {
        const int base = uc * 32;
        for (int tix = tid; tix < 32 * 32; tix += 256) {
            const int r = tix >> 5, c = tix & 31;
            q4[r][c] = ((const float4*)(Qb + (size_t)r * UU))[base + c];
            k4[r][c] = ((const float4*)(Kb + (size_t)r * UU))[base + c];
        }
        if (tid < 32) v4s[tid] = ((const float4*)v)[base + tid];
        __syncthreads();

#pragma unroll 4
        for (int c = 0; c < 32; c++) {
            const float4 kv = k4[jl][c];
            const float4 vv = v4s[c];
#pragma unroll
            for (int r = 0; r < 4; r++) {
                const float4 qv = q4[ib + 8 * r][c];
                acc[r] += vv.x * tanh_ap(qv.x + kv.x);
                acc[r] += vv.y * tanh_ap(qv.y + kv.y);
                acc[r] += vv.z * tanh_ap(qv.z + kv.z);
                acc[r] += vv.w * tanh_ap(qv.w + kv.w);
            }
        }
        __syncthreads();
    }

#pragma unroll
    for (int r = 0; r < 4; r++) {
        const int i = it * 32 + ib + 8 * r;
        g_S[((size_t)(b * SS + i)) * SS + jt * 32 + jl] = acc[r];
    }
}

// Stage 2b: row softmax; emits bf16 hi/lo pair-planes for the pv mma.
__global__ void __launch_bounds__(256)
softmax2()
{
    const int row = blockIdx.x;
    const float* s = g_S + (size_t)row * SS;
    const int tid = threadIdx.x;

    const float2 vv = ((const float2*)s)[tid];
    float m = fmaxf(vv.x, vv.y);
#pragma unroll
    for (int o = 16; o > 0; o >>= 1) m = fmaxf(m, __shfl_xor_sync(0xffffffffu, m, o));
    __shared__ float sm[8];
    __shared__ float ssum[8];
    if ((tid & 31) == 0) sm[tid >> 5] = m;
    __syncthreads();
    float bm = sm[0];
#pragma unroll
    for (int i = 1; i < 8; i++) bm = fmaxf(bm, sm[i]);

    const float L2E = 1.4426950408889634f;
    float e0 = ex2_ap((vv.x - bm) * L2E);
    float e1 = ex2_ap((vv.y - bm) * L2E);
    float su = e0 + e1;
#pragma unroll
    for (int o = 16; o > 0; o >>= 1) su += __shfl_xor_sync(0xffffffffu, su, o);
    if ((tid & 31) == 0) ssum[tid >> 5] = su;
    __syncthreads();
    float bs = 0.f;
#pragma unroll
    for (int i = 0; i < 8; i++) bs += ssum[i];

    const float inv = 1.0f / bs;
    unsigned h, l;
    bsplit2(e0 * inv, e1 * inv, h, l);
    g_SH[(size_t)row * 256 + tid] = h;
    g_SL[(size_t)row * 256 + tid] = l;
}

extern "C" void kernel_launch(void* const* d_in, const int* in_sizes, int n_in,
                              void* d_out, int out_size)
{
    const float* h1 = (const float*)d_in[0];
    const float* h2 = (const float*)d_in[1];
    const float* w  = (const float*)d_in[2];
    const float* b1 = (const float*)d_in[3];
    const float* v  = (const float*)d_in[4];
    // b2 (d_in[5]) unused: softmax is shift-invariant.
    float* out = (float*)d_out;

    conv_all<<<3328, 256>>>(h1, h2, w);

    qk_mma_split<<<dim3(4, 32, 8), 128>>>();
    qk_reduce<<<1024, 256>>>(b1);

    scores_kernel<<<dim3(16, 16, 4), 256>>>(v);
    softmax2<<<2048, 256>>>();

    pv_mma_split<<<dim3(8, 8, 16), 128>>>();
    pv_reduce<<<1024, 256>>>(out);
}